// round 9
// baseline (speedup 1.0000x reference)
#include <cuda_runtime.h>
#include <cuda_fp16.h>

#define D_FEAT 64
#define MAX_NODES 100000
#define MAX_EDGES 1600000

// Scratch (static __device__ arrays -- no allocation).
__device__ int   g_row_ptr[MAX_NODES + 1];
__device__ uint2 g_x16[MAX_NODES * 16];   // fp16 rows: 128B = 16 x uint2 per row
__device__ uint2 g_meta[MAX_EDGES];       // packed (src, ev-bits) per edge

// Fused prep, 3 roles by block range:
//   [0, rp_blocks)              : build row_ptr from sorted targets
//   [rp_blocks, rp+mt_blocks)   : pack (src, ev) -> g_meta  (also L2-warms meta)
//   rest                        : convert x f32 -> fp16, coalesced (lane-strided)
__global__ __launch_bounds__(256) void prep_kernel(
    const float4* __restrict__ xf4, int n_f4,
    const int* __restrict__ tgt, const int* __restrict__ src,
    const float* __restrict__ ev,
    int n_edges, int n_nodes, int rp_blocks, int mt_blocks)
{
    const int b = (int)blockIdx.x;
    if (b < rp_blocks) {
        const int e = b * 256 + threadIdx.x;
        if (e >= n_edges) return;
        const int cur  = __ldg(tgt + e);
        const int prev = (e == 0) ? -1 : __ldg(tgt + e - 1);
        for (int v = prev + 1; v <= cur; ++v) g_row_ptr[v] = e;
        if (e == n_edges - 1) {
            for (int v = cur + 1; v <= n_nodes; ++v) g_row_ptr[v] = n_edges;
        }
    } else if (b < rp_blocks + mt_blocks) {
        // 4 edges per thread, lane-strided for coalescing.
        const int t0 = (b - rp_blocks) * 256 + threadIdx.x;
        const int base = (t0 >> 5) * 128 + (t0 & 31);  // warp owns 128 edges
        #pragma unroll 4
        for (int k = 0; k < 4; ++k) {
            const int e = base + k * 32;
            if (e < n_edges) {
                const int   s = __ldg(src + e);
                const float w = __ldg(ev + e);
                uint2 m;
                m.x = (unsigned int)s;
                m.y = *reinterpret_cast<const unsigned int*>(&w);
                g_meta[e] = m;
            }
        }
    } else {
        // 4 float4 per thread, lane-strided (+32) -> fully coalesced LDG.128.
        const int t0 = (b - rp_blocks - mt_blocks) * 256 + threadIdx.x;
        const int base = (t0 >> 5) * 128 + (t0 & 31);
        #pragma unroll 4
        for (int k = 0; k < 4; ++k) {
            const int i = base + k * 32;
            if (i < n_f4) {
                const float4 a = __ldg(xf4 + i);
                __half2 h0 = __floats2half2_rn(a.x, a.y);
                __half2 h1 = __floats2half2_rn(a.z, a.w);
                uint2 o;
                o.x = *reinterpret_cast<unsigned int*>(&h0);
                o.y = *reinterpret_cast<unsigned int*>(&h1);
                g_x16[i] = o;
            }
        }
    }
}

__device__ __forceinline__ void fma_edge(float& a0, float& a1, float& a2, float& a3,
                                         float w, uint2 raw) {
    const float2 f0 = __half22float2(*reinterpret_cast<const __half2*>(&raw.x));
    const float2 f1 = __half22float2(*reinterpret_cast<const __half2*>(&raw.y));
    a0 = fmaf(w, f0.x, a0);
    a1 = fmaf(w, f0.y, a1);
    a2 = fmaf(w, f1.x, a2);
    a3 = fmaf(w, f1.y, a3);
}

// One warp per output node (R7 structure). Half-warp h serves edges of parity
// h; lane owns 4 features as one uint2 (4 fp16). 4 edge-pairs in flight.
// Metadata now comes from the L2-warm packed g_meta (one LDG.64).
__global__ __launch_bounds__(128) void mp_gather_kernel(
    float* __restrict__ out,   // [n_nodes, 64]
    int n_nodes)
{
    const int warp = (blockIdx.x * blockDim.x + threadIdx.x) >> 5;
    if (warp >= n_nodes) return;
    const int lane = threadIdx.x & 31;
    const int half = lane >> 4;
    const int hl   = lane & 15;
    const int node = warp;

    const int start = __ldg(&g_row_ptr[node]);
    const int end   = __ldg(&g_row_ptr[node + 1]);

    const uint2* __restrict__ xh = g_x16;   // row = 16 uint2
    float a0 = 0.f, a1 = 0.f, a2 = 0.f, a3 = 0.f;

    for (int base = start; base < end; base += 32) {
        const int cnt = min(32, end - base);
        // Cooperative metadata load: lane l owns edge base+l (one LDG.64).
        int   s_l = 0;
        float w_l = 0.f;
        if (lane < cnt) {
            const uint2 m = __ldg(&g_meta[base + lane]);
            s_l = (int)m.x;
            w_l = *reinterpret_cast<const float*>(&m.y);
        }

        const int full = cnt >> 1;   // complete pairs (both parities valid)
        int k = 0;

        // Main path: 4 pairs per step -> 4 independent gathers per lane.
        for (; k + 4 <= full; k += 4) {
            const int j0 = 2 * (k + 0) + half;
            const int j1 = 2 * (k + 1) + half;
            const int j2 = 2 * (k + 2) + half;
            const int j3 = 2 * (k + 3) + half;
            const int s0 = __shfl_sync(0xffffffffu, s_l, j0);
            const int s1 = __shfl_sync(0xffffffffu, s_l, j1);
            const int s2 = __shfl_sync(0xffffffffu, s_l, j2);
            const int s3 = __shfl_sync(0xffffffffu, s_l, j3);
            const uint2 r0 = __ldg(&xh[(size_t)s0 * 16 + hl]);
            const uint2 r1 = __ldg(&xh[(size_t)s1 * 16 + hl]);
            const uint2 r2 = __ldg(&xh[(size_t)s2 * 16 + hl]);
            const uint2 r3 = __ldg(&xh[(size_t)s3 * 16 + hl]);
            const float w0 = __shfl_sync(0xffffffffu, w_l, j0);
            const float w1 = __shfl_sync(0xffffffffu, w_l, j1);
            const float w2 = __shfl_sync(0xffffffffu, w_l, j2);
            const float w3 = __shfl_sync(0xffffffffu, w_l, j3);
            fma_edge(a0, a1, a2, a3, w0, r0);
            fma_edge(a0, a1, a2, a3, w1, r1);
            fma_edge(a0, a1, a2, a3, w2, r2);
            fma_edge(a0, a1, a2, a3, w3, r3);
        }
        // Remaining complete pairs.
        for (; k < full; ++k) {
            const int j = 2 * k + half;
            const int   s = __shfl_sync(0xffffffffu, s_l, j);
            const float w = __shfl_sync(0xffffffffu, w_l, j);
            const uint2 r = __ldg(&xh[(size_t)s * 16 + hl]);
            fma_edge(a0, a1, a2, a3, w, r);
        }
        // Odd trailing edge: half 1 contributes zero (load still valid).
        if (cnt & 1) {
            const int j = cnt - 1;
            const int   s = __shfl_sync(0xffffffffu, s_l, j);
            float       w = __shfl_sync(0xffffffffu, w_l, j);
            if (half) w = 0.f;
            const uint2 r = __ldg(&xh[(size_t)s * 16 + hl]);
            fma_edge(a0, a1, a2, a3, w, r);
        }
    }

    // Combine the two half-warp partial sums.
    a0 += __shfl_xor_sync(0xffffffffu, a0, 16);
    a1 += __shfl_xor_sync(0xffffffffu, a1, 16);
    a2 += __shfl_xor_sync(0xffffffffu, a2, 16);
    a3 += __shfl_xor_sync(0xffffffffu, a3, 16);

    if (half == 0) {
        float4* __restrict__ of4 = (float4*)out;
        of4[(size_t)node * 16 + hl] = make_float4(a0, a1, a2, a3);
    }
}

extern "C" void kernel_launch(void* const* d_in, const int* in_sizes, int n_in,
                              void* d_out, int out_size) {
    const float* x   = (const float*)d_in[0];
    const float* ev  = (const float*)d_in[1];
    const int*   tgt = (const int*)d_in[2];
    const int*   src = (const int*)d_in[3];
    float* out = (float*)d_out;

    const int n_edges = in_sizes[1];
    const int n_nodes = out_size / D_FEAT;
    const int n_f4    = n_nodes * (D_FEAT / 4);

    const int rp_blocks = (n_edges + 255) / 256;
    const int mt_blocks = (n_edges + 1023) / 1024;   // 4 edges/thread
    const int cv_blocks = (n_f4 + 1023) / 1024;      // 4 float4/thread
    prep_kernel<<<rp_blocks + mt_blocks + cv_blocks, 256>>>(
        (const float4*)x, n_f4, tgt, src, ev, n_edges, n_nodes,
        rp_blocks, mt_blocks);

    const int threads = 128;
    const int blocks  = (n_nodes * 32 + threads - 1) / threads;
    mp_gather_kernel<<<blocks, threads>>>(out, n_nodes);
}